// round 11
// baseline (speedup 1.0000x reference)
#include <cuda_runtime.h>
#include <math_constants.h>

#define BATCH   262144
#define GCOMP   25
#define DDIM    4
#define H1      128
#define H2      256
#define H3      200
#define NHEAD   300
#define H3P     224
#define NHEADP  320

#define ROWS    16
#define THREADS 256

// ---- packed f32x2 helpers ----
__device__ __forceinline__ void ffma2(unsigned long long& a,
                                      unsigned long long x,
                                      unsigned long long w) {
    asm("fma.rn.f32x2 %0, %1, %2, %0;" : "+l"(a) : "l"(x), "l"(w));
}
__device__ __forceinline__ unsigned long long pack2(float lo, float hi) {
    unsigned long long r;
    asm("mov.b64 %0, {%1, %2};" : "=l"(r) : "f"(lo), "f"(hi));
    return r;
}
__device__ __forceinline__ float2 unpack2(unsigned long long a) {
    float2 f;
    asm("mov.b64 {%0, %1}, %2;" : "=f"(f.x), "=f"(f.y) : "l"(a));
    return f;
}

// ---- weights packed [kp][half][s][4]:
//   float at kp*(2*CT) + h*CT + s*4 + e  ==  W[4s+2h+(e>>1)][2kp+(e&1)]
// so one LDG.128 per (kp,half) reads 8 lanes x 16B contiguous (1 line). ----
__device__ __align__(16) float g_W2p[H1 * H2];       // 32768
__device__ __align__(16) float g_W3p[H2 * H3P];      // 57344
__device__ __align__(16) float g_Whp[H3 * NHEADP];   // 64000
__device__ __align__(16) float g_b3p[H3P];
__device__ __align__(16) float g_bh [NHEADP];

__global__ void prep_kernel(const float* __restrict__ W2,
                            const float* __restrict__ W3,
                            const float* __restrict__ Wmu,
                            const float* __restrict__ Wsig,
                            const float* __restrict__ Wpai,
                            const float* __restrict__ b3,
                            const float* __restrict__ bmu,
                            const float* __restrict__ bsig,
                            const float* __restrict__ bpai)
{
    const int t = blockIdx.x * blockDim.x + threadIdx.x;
    const int N2 = H1 * H2;
    const int N3 = H2 * H3P;
    const int Nh = H3 * NHEADP;

    if (t < N2) {                         // CT=H2, fan-in H1
        int kp = t / (2 * H2), rem = t % (2 * H2);
        int h = rem / H2, r2 = rem % H2;
        int s = r2 >> 2, e = r2 & 3;
        int col = 4 * s + 2 * h + (e >> 1);
        int k   = 2 * kp + (e & 1);
        g_W2p[t] = W2[col * H1 + k];
    }
    {
        int t2 = t - N2;                  // CT=H3P, fan-in H2
        if (t2 >= 0 && t2 < N3) {
            int kp = t2 / (2 * H3P), rem = t2 % (2 * H3P);
            int h = rem / H3P, r2 = rem % H3P;
            int s = r2 >> 2, e = r2 & 3;
            int col = 4 * s + 2 * h + (e >> 1);
            int k   = 2 * kp + (e & 1);
            g_W3p[t2] = (col < H3) ? W3[col * H2 + k] : 0.f;
        }
    }
    {
        int t3 = t - N2 - N3;             // CT=NHEADP, fan-in H3
        if (t3 >= 0 && t3 < Nh) {
            int kp = t3 / (2 * NHEADP), rem = t3 % (2 * NHEADP);
            int h = rem / NHEADP, r2 = rem % NHEADP;
            int s = r2 >> 2, e = r2 & 3;
            int col = 4 * s + 2 * h + (e >> 1);
            int k   = 2 * kp + (e & 1);
            float v = 0.f;
            if (col < NHEAD) {
                int hh = col / 100, rr = col % 100;
                const float* W = (hh == 0) ? Wmu : ((hh == 1) ? Wsig : Wpai);
                v = W[rr * H3 + k];
            }
            g_Whp[t3] = v;
        }
    }
    {
        int t4 = t - N2 - N3 - Nh;
        if (t4 >= 0 && t4 < H3P)
            g_b3p[t4] = (t4 < H3) ? b3[t4] : 0.f;
    }
    {
        int t5 = t - N2 - N3 - Nh - H3P;
        if (t5 >= 0 && t5 < NHEADP) {
            float v = 0.f;
            if (t5 < NHEAD) {
                int hh = t5 / 100, rr = t5 % 100;
                const float* bb = (hh == 0) ? bmu : ((hh == 1) ? bsig : bpai);
                v = bb[rr];
            }
            g_bh[t5] = v;
        }
    }
}

// ---- SMEM (floats). Activation rows stored with additive skew:
//      addr(r, c) = r*SA + ((r>>2)&3)*4 + c   (SA multiple of 32) ----
#define S_H1 128
#define S_H2 256
#define S_H3 224
#define S_HO 320

#define O_H2    0                       // 16*256+16 = 4112
#define O_H1    4112                    // 16*128+16 = 2064 -> 6176
#define O_H3    6176                    // 16*224+16 = 3600 -> 9776
#define O_HOUT  0                       // 16*320 = 5120 (inside 6176)
#define O_GUM   9776                    // 1600 -> 11376
#define O_X0    11376                   // 48  -> 11424
#define SMEM_FLOATS 11424
#define SMEM_BYTES  (SMEM_FLOATS * 4)   // 45696 B -> 3 blocks/SM

// One 16x32 unit: lane = 4 rows (quartet q) x 4 cols (quad slot).
// Per 4-k step: 4 weight LDG.128 (1 line each) + 4 act LDS.128 + 32 FFMA2.
template<int K, int SA, int CT>
__device__ __forceinline__ void gemmq(const float* __restrict__ act, int q,
                                      const float* __restrict__ wp, int s,
                                      unsigned long long (&acc)[4][4])
{
    const float* p0 = act + (4 * q) * SA + 4 * q;
    const float* p1 = p0 + SA;
    const float* p2 = p1 + SA;
    const float* p3 = p2 + SA;
    const float* wb = wp + s * 4;

#pragma unroll 2
    for (int t4 = 0; t4 < K / 4; t4++) {
        const float* wr = wb + t4 * (4 * CT);          // kp_a = 2*t4
        ulonglong2 waa = *(const ulonglong2*)(wr);             // kp_a cols 0,1
        ulonglong2 wba = *(const ulonglong2*)(wr + CT);        // kp_a cols 2,3
        ulonglong2 wab = *(const ulonglong2*)(wr + 2 * CT);    // kp_b cols 0,1
        ulonglong2 wbb = *(const ulonglong2*)(wr + 3 * CT);    // kp_b cols 2,3

        ulonglong2 x0 = *(const ulonglong2*)(p0 + t4 * 4);
        ulonglong2 x1 = *(const ulonglong2*)(p1 + t4 * 4);
        ulonglong2 x2 = *(const ulonglong2*)(p2 + t4 * 4);
        ulonglong2 x3 = *(const ulonglong2*)(p3 + t4 * 4);

        ffma2(acc[0][0], x0.x, waa.x); ffma2(acc[0][1], x0.x, waa.y);
        ffma2(acc[0][2], x0.x, wba.x); ffma2(acc[0][3], x0.x, wba.y);
        ffma2(acc[0][0], x0.y, wab.x); ffma2(acc[0][1], x0.y, wab.y);
        ffma2(acc[0][2], x0.y, wbb.x); ffma2(acc[0][3], x0.y, wbb.y);

        ffma2(acc[1][0], x1.x, waa.x); ffma2(acc[1][1], x1.x, waa.y);
        ffma2(acc[1][2], x1.x, wba.x); ffma2(acc[1][3], x1.x, wba.y);
        ffma2(acc[1][0], x1.y, wab.x); ffma2(acc[1][1], x1.y, wab.y);
        ffma2(acc[1][2], x1.y, wbb.x); ffma2(acc[1][3], x1.y, wbb.y);

        ffma2(acc[2][0], x2.x, waa.x); ffma2(acc[2][1], x2.x, waa.y);
        ffma2(acc[2][2], x2.x, wba.x); ffma2(acc[2][3], x2.x, wba.y);
        ffma2(acc[2][0], x2.y, wab.x); ffma2(acc[2][1], x2.y, wab.y);
        ffma2(acc[2][2], x2.y, wbb.x); ffma2(acc[2][3], x2.y, wbb.y);

        ffma2(acc[3][0], x3.x, waa.x); ffma2(acc[3][1], x3.x, waa.y);
        ffma2(acc[3][2], x3.x, wba.x); ffma2(acc[3][3], x3.x, wba.y);
        ffma2(acc[3][0], x3.y, wab.x); ffma2(acc[3][1], x3.y, wab.y);
        ffma2(acc[3][2], x3.y, wbb.x); ffma2(acc[3][3], x3.y, wbb.y);
    }
}

__global__ __launch_bounds__(THREADS, 3)
void mdn_kernel(const float* __restrict__ x0,
                const float* __restrict__ randv,
                const float* __restrict__ gumbel,
                const float* __restrict__ W1,
                const float* __restrict__ b1,
                const float* __restrict__ b2,
                float* __restrict__ out)
{
    extern __shared__ float sm[];
    float* h1s   = sm + O_H1;
    float* h2s   = sm + O_H2;
    float* h3s   = sm + O_H3;
    float* houts = sm + O_HOUT;
    float* gums  = sm + O_GUM;
    float* x0s   = sm + O_X0;

    const int t    = threadIdx.x;
    const int w    = t >> 5;
    const int lane = t & 31;
    const int q    = lane >> 3;       // row quartet
    const int slot = lane & 7;        // col quad
    const int row0 = blockIdx.x * ROWS;

    if (t < ROWS * 3) x0s[t] = x0[row0 * 3 + t];
    __syncthreads();

    // phase 1: h1 = relu(x0 @ W1^T + b1), skewed store
#pragma unroll
    for (int i = 0; i < (ROWS * H1) / THREADS; i++) {
        int o = t + i * THREADS;
        int r = o >> 7;
        int c = o & 127;
        float a1 = b1[c];
        a1 = fmaf(x0s[r * 3 + 0], W1[c * 3 + 0], a1);
        a1 = fmaf(x0s[r * 3 + 1], W1[c * 3 + 1], a1);
        a1 = fmaf(x0s[r * 3 + 2], W1[c * 3 + 2], a1);
        h1s[r * S_H1 + ((r >> 2) & 3) * 4 + c] = fmaxf(a1, 0.f);
    }
    __syncthreads();

    unsigned long long acc[4][4];
    const int sidx = slot;            // within-unit col-quad

    // phase 2: K=128, 256 cols, 8 units (1/warp)
    {
        int cb = w * 32 + slot * 4;
        int s  = w * 8 + sidx;
        float4 bb = *(const float4*)&b2[cb];
#pragma unroll
        for (int i = 0; i < 4; i++) {
            acc[i][0] = pack2(bb.x, 0.f); acc[i][1] = pack2(bb.y, 0.f);
            acc[i][2] = pack2(bb.z, 0.f); acc[i][3] = pack2(bb.w, 0.f);
        }
        gemmq<H1, S_H1, H2>(h1s, q, g_W2p, s, acc);
#pragma unroll
        for (int i = 0; i < 4; i++) {
            int r = 4 * q + i;
            float2 c0 = unpack2(acc[i][0]), c1 = unpack2(acc[i][1]);
            float2 c2 = unpack2(acc[i][2]), c3 = unpack2(acc[i][3]);
            *(float4*)&h2s[r * S_H2 + 4 * q + cb] = make_float4(
                fmaxf(c0.x + c0.y, 0.f), fmaxf(c1.x + c1.y, 0.f),
                fmaxf(c2.x + c2.y, 0.f), fmaxf(c3.x + c3.y, 0.f));
        }
    }
    __syncthreads();

    // phase 3: K=256, 224 cols (200 real), 7 units
    if (w < 7) {
        int cb = w * 32 + slot * 4;
        int s  = w * 8 + sidx;
        float4 bb = *(const float4*)&g_b3p[cb];
#pragma unroll
        for (int i = 0; i < 4; i++) {
            acc[i][0] = pack2(bb.x, 0.f); acc[i][1] = pack2(bb.y, 0.f);
            acc[i][2] = pack2(bb.z, 0.f); acc[i][3] = pack2(bb.w, 0.f);
        }
        gemmq<H2, S_H2, H3P>(h2s, q, g_W3p, s, acc);
        if (cb < H3) {
#pragma unroll
            for (int i = 0; i < 4; i++) {
                int r = 4 * q + i;
                float2 c0 = unpack2(acc[i][0]), c1 = unpack2(acc[i][1]);
                float2 c2 = unpack2(acc[i][2]), c3 = unpack2(acc[i][3]);
                *(float4*)&h3s[r * S_H3 + 4 * q + cb] = make_float4(
                    fmaxf(c0.x + c0.y, 0.f), fmaxf(c1.x + c1.y, 0.f),
                    fmaxf(c2.x + c2.y, 0.f), fmaxf(c3.x + c3.y, 0.f));
            }
        }
    }
    __syncthreads();

    for (int i = t; i < ROWS * GCOMP * DDIM; i += THREADS)
        gums[i] = gumbel[row0 * (GCOMP * DDIM) + i];

    // phase 4: K=200, 320 cols (300 real), 10 units; houts plain layout
    for (int u = w; u < 10; u += 8) {
        int cb = u * 32 + slot * 4;
        int s  = u * 8 + sidx;
        float4 bb = *(const float4*)&g_bh[cb];
#pragma unroll
        for (int i = 0; i < 4; i++) {
            acc[i][0] = pack2(bb.x, 0.f); acc[i][1] = pack2(bb.y, 0.f);
            acc[i][2] = pack2(bb.z, 0.f); acc[i][3] = pack2(bb.w, 0.f);
        }
        gemmq<H3, S_H3, NHEADP>(h3s, q, g_Whp, s, acc);
        if (cb < NHEAD) {
#pragma unroll
            for (int i = 0; i < 4; i++) {
                int r = 4 * q + i;
                float2 c0 = unpack2(acc[i][0]), c1 = unpack2(acc[i][1]);
                float2 c2 = unpack2(acc[i][2]), c3 = unpack2(acc[i][3]);
                *(float4*)&houts[r * S_HO + cb] = make_float4(
                    c0.x + c0.y, c1.x + c1.y, c2.x + c2.y, c3.x + c3.y);
            }
        }
    }
    __syncthreads();

    // phase 5: Gumbel-argmax, select, emit
    if (t < ROWS * DDIM) {
        int r = t >> 2, d = t & 3;
        const float* ho = houts + r * S_HO;
        const float* gu = gums + r * (GCOMP * DDIM);
        float best = -CUDART_INF_F;
        int bi = 0;
#pragma unroll
        for (int g = 0; g < GCOMP; g++) {
            float pai = fabsf(ho[200 + g * 4 + d]);
            float sc = logf(pai + 1e-12f) + gu[g * 4 + d];
            if (sc > best) { best = sc; bi = g; }
        }
        float mu = ho[bi * 4 + d];
        float sg = fabsf(ho[100 + bi * 4 + d]);
        int gi = (row0 + r) * 4 + d;
        out[gi] = fmaf(randv[gi], sg, mu);
    }
}

// inputs: 0:x0 1:rand 2:gumbel 3:W1 4:b1 5:W2 6:b2 7:W3 8:b3
//         9:Wmu 10:bmu 11:Wsig 12:bsig 13:Wpai 14:bpai
extern "C" void kernel_launch(void* const* d_in, const int* in_sizes, int n_in,
                              void* d_out, int out_size)
{
    const float* x0    = (const float*)d_in[0];
    const float* randv = (const float*)d_in[1];
    const float* gumb  = (const float*)d_in[2];
    const float* W1    = (const float*)d_in[3];
    const float* b1    = (const float*)d_in[4];
    const float* W2    = (const float*)d_in[5];
    const float* b2    = (const float*)d_in[6];
    const float* W3    = (const float*)d_in[7];
    const float* b3    = (const float*)d_in[8];
    const float* Wmu   = (const float*)d_in[9];
    const float* bmu   = (const float*)d_in[10];
    const float* Wsig  = (const float*)d_in[11];
    const float* bsig  = (const float*)d_in[12];
    const float* Wpai  = (const float*)d_in[13];
    const float* bpai  = (const float*)d_in[14];
    float* out = (float*)d_out;

    cudaFuncSetAttribute(mdn_kernel,
                         cudaFuncAttributeMaxDynamicSharedMemorySize, SMEM_BYTES);

    int prep_elems = H1 * H2 + H2 * H3P + H3 * NHEADP + H3P + NHEADP;
    int prep_blocks = (prep_elems + 255) / 256;
    prep_kernel<<<prep_blocks, 256>>>(W2, W3, Wmu, Wsig, Wpai, b3,
                                      bmu, bsig, bpai);

    int grid = BATCH / ROWS;   // 16384
    mdn_kernel<<<grid, THREADS, SMEM_BYTES>>>(x0, randv, gumb, W1, b1, b2, out);
}

// round 16
// speedup vs baseline: 1.1927x; 1.1927x over previous
#include <cuda_runtime.h>
#include <math_constants.h>
#include <cstdint>

#define BATCH   262144
#define GCOMP   25
#define BROWS   64
#define THREADS 256

// fragment-grid dims (k8 blocks x n8 blocks), tf32 m16n8k8
#define KB2 16
#define NB2 32
#define KB3 32
#define NB3 26
#define KB4 26
#define NB4A 25
#define NB4B 13

// activation SMEM strides (floats), all == 4 (mod 32) -> conflict-free frags
#define SK1 132
#define SK2 260
#define SK3 228
#define HOS 312          // EVEN: float2 stores at ho + r*HOS + n must be 8B-aligned

// SMEM offsets (floats)
#define O_A1  0          // 64*132 = 8448
#define O_A2  8448       // 64*260 = 16640 -> 25088
#define O_A3  25088      // 64*228 = 14592 -> 39680
#define O_GUM 39680      // 6400 -> 46080
#define O_HO  0          // 64*312 = 19968 (overlays A1+A2 after layer 3)
#define SMEM_FLOATS 46080
#define SMEM_BYTES (SMEM_FLOATS * 4)   // 184320

// ---- pre-baked tf32 B fragments: [comp][kb][nb][lane]{b0,b1} ----
__device__ __align__(16) uint32_t g_B2 [2 * KB2 * NB2  * 64];
__device__ __align__(16) uint32_t g_B3 [2 * KB3 * NB3  * 64];
__device__ __align__(16) uint32_t g_B4a[2 * KB4 * NB4A * 64];
__device__ __align__(16) uint32_t g_B4b[2 * KB4 * NB4B * 64];

__device__ __forceinline__ uint32_t tf32_hi(float v) {
    uint32_t h;
    asm("cvt.rna.tf32.f32 %0, %1;" : "=r"(h) : "f"(v));
    return h;
}
__device__ __forceinline__ void tf32_split(float v, uint32_t& h, uint32_t& l) {
    h = tf32_hi(v);
    float lf = v - __uint_as_float(h);
    l = tf32_hi(lf);
}
__device__ __forceinline__ void mma_tf32(float* c, const uint32_t* a,
                                         uint32_t b0, uint32_t b1) {
    asm volatile("mma.sync.aligned.m16n8k8.row.col.f32.tf32.tf32.f32 "
        "{%0,%1,%2,%3}, {%4,%5,%6,%7}, {%8,%9}, {%0,%1,%2,%3};"
        : "+f"(c[0]), "+f"(c[1]), "+f"(c[2]), "+f"(c[3])
        : "r"(a[0]), "r"(a[1]), "r"(a[2]), "r"(a[3]), "r"(b0), "r"(b1));
}

// ---------------- prep: bake split-tf32 B fragments -------------------------
__global__ void prep_kernel(const float* __restrict__ W2,
                            const float* __restrict__ W3,
                            const float* __restrict__ Wmu,
                            const float* __restrict__ Wsig,
                            const float* __restrict__ Wpai)
{
    const int idx = blockIdx.x * blockDim.x + threadIdx.x;
    const int C2  = 2 * KB2 * NB2  * 64;
    const int C3  = 2 * KB3 * NB3  * 64;
    const int C4a = 2 * KB4 * NB4A * 64;
    const int C4b = 2 * KB4 * NB4B * 64;

    int e = idx;
    uint32_t* dst = nullptr;
    int KB = 0, NB = 0, layer = 0;
    if (e < C2)               { dst = g_B2;  KB = KB2; NB = NB2;  layer = 2; }
    else if ((e -= C2) < C3)  { dst = g_B3;  KB = KB3; NB = NB3;  layer = 3; }
    else if ((e -= C3) < C4a) { dst = g_B4a; KB = KB4; NB = NB4A; layer = 4; }
    else if ((e -= C4a) < C4b){ dst = g_B4b; KB = KB4; NB = NB4B; layer = 5; }
    else return;

    int j    = e & 1;                  // b0 / b1
    int lane = (e >> 1) & 31;
    int blk  = e >> 6;                 // (comp*KB + kb)*NB + nb
    int nb   = blk % NB;
    int kb   = (blk / NB) % KB;
    int comp = blk / (NB * KB);

    int n = nb * 8 + (lane >> 2);
    int k = kb * 8 + (lane & 3) + j * 4;

    float v = 0.f;
    if (layer == 2) {
        v = W2[n * 128 + k];
    } else if (layer == 3) {
        if (n < 200) v = W3[n * 256 + k];
    } else if (layer == 4) {
        if (k < 200) v = (n < 100) ? Wmu[n * 200 + k] : Wsig[(n - 100) * 200 + k];
    } else {
        if (n < 100 && k < 200) v = Wpai[n * 200 + k];
    }
    uint32_t h = tf32_hi(v);
    if (comp == 0) dst[e] = h;
    else           dst[e] = tf32_hi(v - __uint_as_float(h));
}

// ---------------- warp GEMM: M=64 x N=NB*8 x K=KB*8, 3xTF32 -----------------
// A in SMEM as fp32 (stride SKE, SKE % 32 == 4); split to tf32 in regs.
template<int KB, int NB, int SKE, int MAXI>
__device__ __forceinline__ void gemm_tf32(
    const float* __restrict__ aS,
    const uint2* __restrict__ Bh, const uint2* __restrict__ Bl,
    int w, int lane, float (&acc)[MAXI][4][4])
{
    const int ar = lane >> 2;          // 0..7
    const int ac = lane & 3;           // 0..3
#pragma unroll
    for (int i = 0; i < MAXI; i++)
#pragma unroll
        for (int rb = 0; rb < 4; rb++)
#pragma unroll
            for (int q = 0; q < 4; q++) acc[i][rb][q] = 0.f;

    for (int kb = 0; kb < KB; kb++) {
        uint32_t AH[4][4], AL[4][4];
        const int c0 = kb * 8 + ac;
#pragma unroll
        for (int rb = 0; rb < 4; rb++) {
            const float* base = aS + (rb * 16 + ar) * SKE;
            float v0 = base[c0];               // (r, k)
            float v1 = base[8 * SKE + c0];     // (r+8, k)
            float v2 = base[c0 + 4];           // (r, k+4)
            float v3 = base[8 * SKE + c0 + 4]; // (r+8, k+4)
            tf32_split(v0, AH[rb][0], AL[rb][0]);
            tf32_split(v1, AH[rb][1], AL[rb][1]);
            tf32_split(v2, AH[rb][2], AL[rb][2]);
            tf32_split(v3, AH[rb][3], AL[rb][3]);
        }
#pragma unroll
        for (int i = 0; i < MAXI; i++) {
            int nb = w + i * 8;
            if (nb < NB) {
                uint2 bh = Bh[(kb * NB + nb) * 32 + lane];
                uint2 bl = Bl[(kb * NB + nb) * 32 + lane];
#pragma unroll
                for (int rb = 0; rb < 4; rb++) mma_tf32(acc[i][rb], AH[rb], bh.x, bh.y);
#pragma unroll
                for (int rb = 0; rb < 4; rb++) mma_tf32(acc[i][rb], AL[rb], bh.x, bh.y);
#pragma unroll
                for (int rb = 0; rb < 4; rb++) mma_tf32(acc[i][rb], AH[rb], bl.x, bl.y);
            }
        }
    }
}

__global__ __launch_bounds__(THREADS)
void mdn_mma_kernel(const float* __restrict__ x0,
                    const float* __restrict__ randv,
                    const float* __restrict__ gumbel,
                    const float* __restrict__ W1,
                    const float* __restrict__ b1,
                    const float* __restrict__ b2,
                    const float* __restrict__ b3,
                    const float* __restrict__ bmu,
                    const float* __restrict__ bsig,
                    const float* __restrict__ bpai,
                    float* __restrict__ out)
{
    extern __shared__ float sm[];
    const int t    = threadIdx.x;
    const int w    = t >> 5;
    const int lane = t & 31;
    const int row0 = blockIdx.x * BROWS;
    float* a1   = sm + O_A1;
    float* a2   = sm + O_A2;
    float* a3   = sm + O_A3;
    float* gums = sm + O_GUM;
    float* ho   = sm + O_HO;

    // ---- phase 1: h1 = relu(x0 @ W1^T + b1) -> fp32 A1 ----
    {
        int r  = t >> 2;            // 0..63
        int cb = (t & 3) * 32;
        float xr0 = x0[(row0 + r) * 3 + 0];
        float xr1 = x0[(row0 + r) * 3 + 1];
        float xr2 = x0[(row0 + r) * 3 + 2];
        float* arow = a1 + r * SK1;
#pragma unroll 8
        for (int jj = 0; jj < 32; jj++) {
            int c = cb + jj;
            float v = b1[c];
            v = fmaf(xr0, W1[c * 3 + 0], v);
            v = fmaf(xr1, W1[c * 3 + 1], v);
            v = fmaf(xr2, W1[c * 3 + 2], v);
            arow[c] = fmaxf(v, 0.f);
        }
    }
    for (int i = t; i < BROWS * 100; i += THREADS)
        gums[i] = gumbel[row0 * 100 + i];
    __syncthreads();

    const int tq = lane >> 2;        // D-frag row in block
    const int tc = (lane & 3) * 2;   // D-frag col pair base

    // ---- layer 2: 64x256x128 -> A2 (fp32) ----
    {
        float acc[4][4][4];
        gemm_tf32<KB2, NB2, SK1, 4>(a1,
            (const uint2*)g_B2, (const uint2*)g_B2 + KB2 * NB2 * 32, w, lane, acc);
#pragma unroll
        for (int i = 0; i < 4; i++) {
            int n = (w + i * 8) * 8 + tc;
            float bb0 = b2[n], bb1 = b2[n + 1];
#pragma unroll
            for (int rb = 0; rb < 4; rb++) {
                int r1 = rb * 16 + tq;
                *(float2*)(a2 + r1 * SK2 + n) = make_float2(
                    fmaxf(acc[i][rb][0] + bb0, 0.f), fmaxf(acc[i][rb][1] + bb1, 0.f));
                *(float2*)(a2 + (r1 + 8) * SK2 + n) = make_float2(
                    fmaxf(acc[i][rb][2] + bb0, 0.f), fmaxf(acc[i][rb][3] + bb1, 0.f));
            }
        }
    }
    __syncthreads();

    // ---- layer 3: 64x208x256 -> A3 (cols 200..207 exact zero) ----
    {
        float acc[4][4][4];
        gemm_tf32<KB3, NB3, SK2, 4>(a2,
            (const uint2*)g_B3, (const uint2*)g_B3 + KB3 * NB3 * 32, w, lane, acc);
#pragma unroll
        for (int i = 0; i < 4; i++) {
            int nb = w + i * 8;
            if (nb < NB3) {
                int n = nb * 8 + tc;
                float bb0 = (n < 200) ? b3[n] : 0.f;
                float bb1 = (n + 1 < 200) ? b3[n + 1] : 0.f;
#pragma unroll
                for (int rb = 0; rb < 4; rb++) {
                    int r1 = rb * 16 + tq;
                    *(float2*)(a3 + r1 * SK3 + n) = make_float2(
                        fmaxf(acc[i][rb][0] + bb0, 0.f), fmaxf(acc[i][rb][1] + bb1, 0.f));
                    *(float2*)(a3 + (r1 + 8) * SK3 + n) = make_float2(
                        fmaxf(acc[i][rb][2] + bb0, 0.f), fmaxf(acc[i][rb][3] + bb1, 0.f));
                }
            }
        }
    }
    __syncthreads();

    // ---- layer 4a: mu+sig (N=200) -> ho cols 0..199 ----
    {
        float acc[4][4][4];
        gemm_tf32<KB4, NB4A, SK3, 4>(a3,
            (const uint2*)g_B4a, (const uint2*)g_B4a + KB4 * NB4A * 32, w, lane, acc);
#pragma unroll
        for (int i = 0; i < 4; i++) {
            int nb = w + i * 8;
            if (nb < NB4A) {
                int n = nb * 8 + tc;
                float bb0 = (n < 100) ? bmu[n] : bsig[n - 100];
                float bb1 = (n + 1 < 100) ? bmu[n + 1] : bsig[n + 1 - 100];
#pragma unroll
                for (int rb = 0; rb < 4; rb++) {
                    int r1 = rb * 16 + tq;
                    *(float2*)(ho + r1 * HOS + n) =
                        make_float2(acc[i][rb][0] + bb0, acc[i][rb][1] + bb1);
                    *(float2*)(ho + (r1 + 8) * HOS + n) =
                        make_float2(acc[i][rb][2] + bb0, acc[i][rb][3] + bb1);
                }
            }
        }
    }

    // ---- layer 4b: pai (N=104, 100 real) -> ho cols 200..303 ----
    {
        float acc[2][4][4];
        gemm_tf32<KB4, NB4B, SK3, 2>(a3,
            (const uint2*)g_B4b, (const uint2*)g_B4b + KB4 * NB4B * 32, w, lane, acc);
#pragma unroll
        for (int i = 0; i < 2; i++) {
            int nb = w + i * 8;
            if (nb < NB4B) {
                int n = nb * 8 + tc;
                float bb0 = (n < 100) ? bpai[n] : 0.f;
                float bb1 = (n + 1 < 100) ? bpai[n + 1] : 0.f;
#pragma unroll
                for (int rb = 0; rb < 4; rb++) {
                    int r1 = rb * 16 + tq;
                    if (n < 104) {
                        *(float2*)(ho + r1 * HOS + 200 + n) =
                            make_float2(acc[i][rb][0] + bb0, acc[i][rb][1] + bb1);
                        *(float2*)(ho + (r1 + 8) * HOS + 200 + n) =
                            make_float2(acc[i][rb][2] + bb0, acc[i][rb][3] + bb1);
                    }
                }
            }
        }
    }
    __syncthreads();

    // ---- phase 5: Gumbel-argmax, select, emit (one item per thread) ----
    {
        int r = t >> 2, d = t & 3;
        const float* hrow = ho + r * HOS;
        const float* gu = gums + r * 100;
        float best = -CUDART_INF_F;
        int bi = 0;
#pragma unroll
        for (int g = 0; g < GCOMP; g++) {
            float pai = fabsf(hrow[200 + g * 4 + d]);
            float sc = logf(pai + 1e-12f) + gu[g * 4 + d];
            if (sc > best) { best = sc; bi = g; }
        }
        float mu = hrow[bi * 4 + d];
        float sg = fabsf(hrow[100 + bi * 4 + d]);
        int gi = (row0 + r) * 4 + d;
        out[gi] = fmaf(randv[gi], sg, mu);
    }
}

// inputs: 0:x0 1:rand 2:gumbel 3:W1 4:b1 5:W2 6:b2 7:W3 8:b3
//         9:Wmu 10:bmu 11:Wsig 12:bsig 13:Wpai 14:bpai
extern "C" void kernel_launch(void* const* d_in, const int* in_sizes, int n_in,
                              void* d_out, int out_size)
{
    const float* x0    = (const float*)d_in[0];
    const float* randv = (const float*)d_in[1];
    const float* gumb  = (const float*)d_in[2];
    const float* W1    = (const float*)d_in[3];
    const float* b1    = (const float*)d_in[4];
    const float* W2    = (const float*)d_in[5];
    const float* b2    = (const float*)d_in[6];
    const float* W3    = (const float*)d_in[7];
    const float* b3    = (const float*)d_in[8];
    const float* Wmu   = (const float*)d_in[9];
    const float* bmu   = (const float*)d_in[10];
    const float* Wsig  = (const float*)d_in[11];
    const float* bsig  = (const float*)d_in[12];
    const float* Wpai  = (const float*)d_in[13];
    const float* bpai  = (const float*)d_in[14];
    float* out = (float*)d_out;

    cudaFuncSetAttribute(mdn_mma_kernel,
                         cudaFuncAttributeMaxDynamicSharedMemorySize, SMEM_BYTES);

    int prep_elems = 2 * 64 * (KB2 * NB2 + KB3 * NB3 + KB4 * NB4A + KB4 * NB4B);
    int prep_blocks = (prep_elems + 255) / 256;
    prep_kernel<<<prep_blocks, 256>>>(W2, W3, Wmu, Wsig, Wpai);

    int grid = BATCH / BROWS;   // 4096
    mdn_mma_kernel<<<grid, THREADS, SMEM_BYTES>>>(
        x0, randv, gumb, W1, b1, b2, b3, bmu, bsig, bpai, out);
}